// round 2
// baseline (speedup 1.0000x reference)
#include <cuda_runtime.h>

#define NN     50000
#define EE     800000
#define HH     2
#define DD     32
#define HD     64      // H*D
#define INDIM  64
#define ERELN  200000
#define DRELN  32

// ---------------- scratch (static __device__, no allocation) ----------------
__device__ float    g_hp[NN * HD];
__device__ float    g_esrc[NN * HH];
__device__ float    g_edst[NN * HH];
__device__ float    g_vmid[NN * HD];
__device__ float    g_smid[NN * HH];
__device__ float    g_vrel[ERELN * HD];
__device__ float    g_srel[ERELN * HH];
__device__ float    g_logit[EE * HH];
__device__ unsigned g_m[NN * HH];
__device__ float    g_denom[NN * HH];
__device__ float    g_rst[NN * HD];

// ordered-uint encoding for float atomicMax
__device__ __forceinline__ unsigned ford(float f) {
    unsigned u = __float_as_uint(f);
    return (u >> 31) ? ~u : (u | 0x80000000u);
}
__device__ __forceinline__ float forddec(unsigned u) {
    return __uint_as_float((u >> 31) ? (u & 0x7fffffffu) : ~u);
}

// ---------------- init ----------------
__global__ void k_init() {
    int i = blockIdx.x * blockDim.x + threadIdx.x;
    if (i < NN * HD) g_rst[i] = 0.f;
    if (i < NN * HH) { g_m[i] = 0x007FFFFFu; /* ord(-inf) */ g_denom[i] = 0.f; }
}

// ---------------- target node projection: hp, e_src, e_dst ----------------
// block = 256 threads = 4 nodes x 64 out-cols; each warp = (node, head)
__global__ void k_proj_target(const float* __restrict__ h,
                              const float* __restrict__ W,
                              const float* __restrict__ b,
                              const float* __restrict__ asrc,
                              const float* __restrict__ adst) {
    __shared__ float sW[INDIM * HD];
    __shared__ float sx[4 * INDIM];
    int tid = threadIdx.x;
    int n0  = blockIdx.x * 4;
    for (int i = tid; i < INDIM * HD; i += 256) sW[i] = W[i];
    {
        int nl = tid >> 6, c = tid & 63;
        sx[tid] = h[(n0 + nl) * INDIM + c];
    }
    __syncthreads();
    int nl = tid >> 6, c = tid & 63;
    int n  = n0 + nl;
    float acc = b[c];
#pragma unroll
    for (int k = 0; k < INDIM; k++) acc = fmaf(sx[nl * INDIM + k], sW[k * HD + c], acc);
    g_hp[n * HD + c] = acc;
    float r  = fmaxf(acc, 0.f);
    float vs = r * asrc[c];
    float vd = r * adst[c];
#pragma unroll
    for (int o = 16; o > 0; o >>= 1) {
        vs += __shfl_down_sync(0xffffffffu, vs, o);
        vd += __shfl_down_sync(0xffffffffu, vd, o);
    }
    if ((c & 31) == 0) {
        int hd = c >> 5;
        g_esrc[n * HH + hd] = vs;
        g_edst[n * HH + hd] = vd;
    }
}

// ---------------- mid node projection: v_mid (= mid_f @ W_edge[0:32]), s_mid ----------------
__global__ void k_proj_mid(const float* __restrict__ x,
                           const float* __restrict__ W,
                           const float* __restrict__ b,
                           const float* __restrict__ aedge,
                           const float* __restrict__ We) {
    __shared__ float sW[INDIM * HD];
    __shared__ float sWe[DD * DD];
    __shared__ float sx[4 * INDIM];
    __shared__ float sf[4 * HD];
    int tid = threadIdx.x;
    int n0  = blockIdx.x * 4;
    for (int i = tid; i < INDIM * HD; i += 256) sW[i] = W[i];
    for (int i = tid; i < DD * DD; i += 256)    sWe[i] = We[i];        // rows 0..31
    {
        int nl = tid >> 6, c = tid & 63;
        sx[tid] = x[(n0 + nl) * INDIM + c];
    }
    __syncthreads();
    int nl = tid >> 6, c = tid & 63;
    int n  = n0 + nl;
    float acc = b[c];
#pragma unroll
    for (int k = 0; k < INDIM; k++) acc = fmaf(sx[nl * INDIM + k], sW[k * HD + c], acc);
    sf[tid] = acc;
    int hd = c >> 5, d = c & 31;
    float v = fmaxf(acc, 0.f) * aedge[hd * 64 + d];
#pragma unroll
    for (int o = 16; o > 0; o >>= 1) v += __shfl_down_sync(0xffffffffu, v, o);
    if (d == 0) g_smid[n * HH + hd] = v;
    __syncthreads();
    float vm = 0.f;
#pragma unroll
    for (int dd = 0; dd < DD; dd++)
        vm = fmaf(sf[nl * HD + hd * DD + dd], sWe[dd * DD + d], vm);
    g_vmid[n * HD + c] = vm;
}

// ---------------- rel edge-feat projection: v_rel (= rel_f @ W_edge[32:64]), s_rel ----------------
__global__ void k_proj_rel(const float* __restrict__ x,
                           const float* __restrict__ W,
                           const float* __restrict__ b,
                           const float* __restrict__ aedge,
                           const float* __restrict__ We) {
    __shared__ float sW[DRELN * HD];
    __shared__ float sWe[DD * DD];
    __shared__ float sx[4 * DRELN];
    __shared__ float sf[4 * HD];
    int tid = threadIdx.x;
    int n0  = blockIdx.x * 4;
    for (int i = tid; i < DRELN * HD; i += 256) sW[i] = W[i];
    for (int i = tid; i < DD * DD; i += 256)    sWe[i] = We[DD * DD + i]; // rows 32..63
    if (tid < 4 * DRELN) sx[tid] = x[n0 * DRELN + tid];                   // rows contiguous
    __syncthreads();
    int nl = tid >> 6, c = tid & 63;
    int n  = n0 + nl;
    float acc = b[c];
#pragma unroll
    for (int k = 0; k < DRELN; k++) acc = fmaf(sx[nl * DRELN + k], sW[k * HD + c], acc);
    sf[tid] = acc;
    int hd = c >> 5, d = c & 31;
    float v = fmaxf(acc, 0.f) * aedge[hd * 64 + 32 + d];
#pragma unroll
    for (int o = 16; o > 0; o >>= 1) v += __shfl_down_sync(0xffffffffu, v, o);
    if (d == 0) g_srel[n * HH + hd] = v;
    __syncthreads();
    float vr = 0.f;
#pragma unroll
    for (int dd = 0; dd < DD; dd++)
        vr = fmaf(sf[nl * HD + hd * DD + dd], sWe[dd * DD + d], vr);
    g_vrel[n * HD + c] = vr;
}

// ---------------- edge pass A: logits + segment max ----------------
__global__ void k_edge_logit(const int* __restrict__ src, const int* __restrict__ dst,
                             const int* __restrict__ hn,  const int* __restrict__ he) {
    int e = blockIdx.x * blockDim.x + threadIdx.x;
    if (e >= EE) return;
    int s = src[e], t = dst[e], mn = hn[e], r = he[e];
#pragma unroll
    for (int hd = 0; hd < HH; hd++) {
        float L = g_esrc[s * HH + hd] + g_edst[t * HH + hd]
                + g_smid[mn * HH + hd] + g_srel[r * HH + hd];
        g_logit[e * HH + hd] = L;
        atomicMax(&g_m[t * HH + hd], ford(L));
    }
}

// ---------------- edge pass B: exp, denom, unnormalized weighted scatter-sum ----------------
// one warp per edge; lane l handles out-cols l (head 0) and l+32 (head 1)
__global__ void k_edge_agg(const int* __restrict__ src, const int* __restrict__ dst,
                           const int* __restrict__ hn,  const int* __restrict__ he) {
    int gw   = (blockIdx.x * blockDim.x + threadIdx.x) >> 5;
    int lane = threadIdx.x & 31;
    if (gw >= EE) return;
    int e = gw;
    int s = src[e], t = dst[e], mn = hn[e], r = he[e];
    float ex0 = __expf(g_logit[e * 2 + 0] - forddec(g_m[t * 2 + 0]));
    float ex1 = __expf(g_logit[e * 2 + 1] - forddec(g_m[t * 2 + 1]));
    if (lane == 0) atomicAdd(&g_denom[t * 2 + 0], ex0);
    if (lane == 1) atomicAdd(&g_denom[t * 2 + 1], ex1);
    int c0 = lane, c1 = lane + 32;
    float v0 = ex0 * (g_hp[s * HD + c0] + g_vmid[mn * HD + c0] + g_vrel[r * HD + c0]);
    float v1 = ex1 * (g_hp[s * HD + c1] + g_vmid[mn * HD + c1] + g_vrel[r * HD + c1]);
    atomicAdd(&g_rst[t * HD + c0], v0);
    atomicAdd(&g_rst[t * HD + c1], v1);
}

// ---------------- final: normalize by denom, +b_edge, residual, relu, L2-normalize ----------------
__global__ void k_final(const float* __restrict__ b_edge, float* __restrict__ out) {
    int tid = threadIdx.x;
    int nl  = tid >> 6, c = tid & 63;
    int n   = blockIdx.x * 4 + nl;
    int hd  = c >> 5, d = c & 31;
    float den = g_denom[n * HH + hd];
    float rst = (den > 0.f) ? g_rst[n * HD + c] / den : 0.f;
    float val = fmaxf(rst + b_edge[d] + g_hp[n * HD + c], 0.f);
    float ss  = val * val;
#pragma unroll
    for (int o = 16; o > 0; o >>= 1) ss += __shfl_down_sync(0xffffffffu, ss, o);
    __shared__ float sp[8];
    if ((tid & 31) == 0) sp[tid >> 5] = ss;
    __syncthreads();
    float tot  = sp[nl * 2] + sp[nl * 2 + 1];
    float norm = fmaxf(sqrtf(tot), 1e-12f);
    out[n * HD + c] = val / norm;
}

extern "C" void kernel_launch(void* const* d_in, const int* in_sizes, int n_in,
                              void* d_out, int out_size) {
    const float* h         = (const float*)d_in[0];
    const float* W_t       = (const float*)d_in[1];
    const float* b_t       = (const float*)d_in[2];
    const float* nfeat_mid = (const float*)d_in[3];
    const float* W_mid     = (const float*)d_in[4];
    const float* b_mid     = (const float*)d_in[5];
    const float* efeat_rel = (const float*)d_in[6];
    const float* W_rel     = (const float*)d_in[7];
    const float* b_rel     = (const float*)d_in[8];
    const float* attn_src  = (const float*)d_in[9];
    const float* attn_dst  = (const float*)d_in[10];
    const float* attn_edge = (const float*)d_in[11];
    const float* W_edge    = (const float*)d_in[12];
    const float* b_edge    = (const float*)d_in[13];
    const int*   src_idx   = (const int*)d_in[14];
    const int*   dst_idx   = (const int*)d_in[15];
    const int*   hn        = (const int*)d_in[16];
    const int*   he        = (const int*)d_in[17];
    float* out = (float*)d_out;

    k_init<<<(NN * HD + 255) / 256, 256>>>();
    k_proj_target<<<NN / 4, 256>>>(h, W_t, b_t, attn_src, attn_dst);
    k_proj_mid<<<NN / 4, 256>>>(nfeat_mid, W_mid, b_mid, attn_edge, W_edge);
    k_proj_rel<<<ERELN / 4, 256>>>(efeat_rel, W_rel, b_rel, attn_edge, W_edge);
    k_edge_logit<<<(EE + 255) / 256, 256>>>(src_idx, dst_idx, hn, he);
    k_edge_agg<<<(EE * 32 + 255) / 256, 256>>>(src_idx, dst_idx, hn, he);
    k_final<<<NN / 4, 256>>>(b_edge, out);
}

// round 3
// speedup vs baseline: 1.6855x; 1.6855x over previous
#include <cuda_runtime.h>

#define NN     50000
#define EE     800000
#define HH     2
#define DD     32
#define HD     64      // H*D
#define INDIM  64
#define ERELN  200000
#define DRELN  32

// ---------------- scratch (static __device__, no allocation) ----------------
__device__ float4   g_hp4[NN * 16];        // hp, float4-aligned
__device__ float4   g_vmid4[NN * 16];      // x_mid @ M_mid  (bias folded out)
__device__ float4   g_vrel4[ERELN * 16];   // x_rel @ M_rel  (bias folded out)
__device__ float2   g_es2[NN];             // e_src per (n,h)
__device__ float2   g_ed2[NN];             // e_dst
__device__ float2   g_sm2[NN];             // s_mid
__device__ float2   g_sr2[ERELN];          // s_rel
__device__ float2   g_logit2[EE];
__device__ unsigned g_m[NN * HH];
__device__ float    g_denom[NN * HH];
__device__ float4   g_rst4[NN * 16];
__device__ float    g_Mmid[INDIM * HD];    // W_mid @ We[0:32]  per head
__device__ float    g_Mrel[DRELN * HD];    // W_rel @ We[32:64] per head
__device__ float    g_vb[HD];              // (b_mid@We_top + b_rel@We_bot)

__device__ __forceinline__ unsigned ford(float f) {
    unsigned u = __float_as_uint(f);
    return (u >> 31) ? ~u : (u | 0x80000000u);
}
__device__ __forceinline__ float forddec(unsigned u) {
    return __uint_as_float((u >> 31) ? (u & 0x7fffffffu) : ~u);
}
__device__ __forceinline__ void red_add_v4(float* p, float4 v) {
    asm volatile("red.global.add.v4.f32 [%0], {%1,%2,%3,%4};"
                 :: "l"(p), "f"(v.x), "f"(v.y), "f"(v.z), "f"(v.w) : "memory");
}

// ---------------- init ----------------
__global__ void k_init() {
    int i = blockIdx.x * blockDim.x + threadIdx.x;
    if (i < NN * 16) g_rst4[i] = make_float4(0.f, 0.f, 0.f, 0.f);
    if (i < NN * HH) { g_m[i] = 0x007FFFFFu; g_denom[i] = 0.f; }
}

// ---------------- precompute fused weight matrices ----------------
__global__ void k_prep(const float* __restrict__ W_mid, const float* __restrict__ W_rel,
                       const float* __restrict__ b_mid, const float* __restrict__ b_rel,
                       const float* __restrict__ We) {
    __shared__ float sWe[64 * 32];
    int tid = threadIdx.x;
    for (int i = tid; i < 2048; i += 256) sWe[i] = We[i];
    __syncthreads();
    for (int idx = tid; idx < INDIM * HD; idx += 256) {
        int k = idx >> 6, c = idx & 63, h = c >> 5, d = c & 31;
        float acc = 0.f;
        for (int dd = 0; dd < 32; dd++)
            acc = fmaf(W_mid[k * 64 + h * 32 + dd], sWe[dd * 32 + d], acc);
        g_Mmid[idx] = acc;
    }
    for (int idx = tid; idx < DRELN * HD; idx += 256) {
        int k = idx >> 6, c = idx & 63, h = c >> 5, d = c & 31;
        float acc = 0.f;
        for (int dd = 0; dd < 32; dd++)
            acc = fmaf(W_rel[k * 64 + h * 32 + dd], sWe[(32 + dd) * 32 + d], acc);
        g_Mrel[idx] = acc;
    }
    if (tid < HD) {
        int h = tid >> 5, d = tid & 31;
        float acc = 0.f;
        for (int dd = 0; dd < 32; dd++) {
            acc = fmaf(b_mid[h * 32 + dd], sWe[dd * 32 + d], acc);
            acc = fmaf(b_rel[h * 32 + dd], sWe[(32 + dd) * 32 + d], acc);
        }
        g_vb[tid] = acc;
    }
}

// ---------------- target projection: hp, e_src, e_dst ----------------
// 256 thr = 8 warps = 4 row-slots x 2 heads; 32 rows/block; W column in regs
__global__ void __launch_bounds__(256) k_proj_target(const float* __restrict__ x,
                              const float* __restrict__ W,
                              const float* __restrict__ b,
                              const float* __restrict__ asrc,
                              const float* __restrict__ adst) {
    __shared__ float sx[32 * INDIM];
    int tid = threadIdx.x, w = tid >> 5, lane = tid & 31;
    int slot = w >> 1, head = w & 1;
    int n0 = blockIdx.x * 32;
    int nrows = min(32, NN - n0);
    for (int i = tid; i < nrows * INDIM; i += 256) sx[i] = x[n0 * INDIM + i];
    float wreg[INDIM];
#pragma unroll
    for (int k = 0; k < INDIM; k++) wreg[k] = W[k * HD + head * 32 + lane];
    float bb = b[head * 32 + lane];
    float as = asrc[head * 32 + lane], ad = adst[head * 32 + lane];
    __syncthreads();
    float* hp = (float*)g_hp4;
    for (int row = slot; row < nrows; row += 4) {
        int n = n0 + row;
        float acc = bb;
#pragma unroll
        for (int k = 0; k < INDIM; k++) acc = fmaf(sx[row * INDIM + k], wreg[k], acc);
        hp[n * HD + head * 32 + lane] = acc;
        float r = fmaxf(acc, 0.f);
        float vs = r * as, vd = r * ad;
#pragma unroll
        for (int o = 16; o > 0; o >>= 1) {
            vs += __shfl_down_sync(0xffffffffu, vs, o);
            vd += __shfl_down_sync(0xffffffffu, vd, o);
        }
        if (lane == 0) {
            ((float*)&g_es2[n])[head] = vs;
            ((float*)&g_ed2[n])[head] = vd;
        }
    }
}

// ---------------- mid projection: v_mid = x@M_mid, s_mid ----------------
// 128 thr = 4 warps = 2 slots x 2 heads; 16 rows/block
__global__ void __launch_bounds__(128, 3) k_proj_mid(const float* __restrict__ x,
                           const float* __restrict__ W,
                           const float* __restrict__ b,
                           const float* __restrict__ aedge) {
    __shared__ float sx[16 * INDIM];
    int tid = threadIdx.x, w = tid >> 5, lane = tid & 31;
    int slot = w >> 1, head = w & 1;
    int n0 = blockIdx.x * 16;
    for (int i = tid; i < 16 * INDIM; i += 128) sx[i] = x[n0 * INDIM + i];
    float wreg[INDIM], mreg[INDIM];
#pragma unroll
    for (int k = 0; k < INDIM; k++) {
        wreg[k] = W[k * HD + head * 32 + lane];
        mreg[k] = g_Mmid[k * HD + head * 32 + lane];
    }
    float bb = b[head * 32 + lane];
    float av = aedge[head * 64 + lane];
    __syncthreads();
    float* vm = (float*)g_vmid4;
    for (int row = slot; row < 16; row += 2) {
        int n = n0 + row;
        float acc = bb, vacc = 0.f;
#pragma unroll
        for (int k = 0; k < INDIM; k++) {
            float xk = sx[row * INDIM + k];
            acc  = fmaf(xk, wreg[k], acc);
            vacc = fmaf(xk, mreg[k], vacc);
        }
        vm[n * HD + head * 32 + lane] = vacc;
        float s = fmaxf(acc, 0.f) * av;
#pragma unroll
        for (int o = 16; o > 0; o >>= 1) s += __shfl_down_sync(0xffffffffu, s, o);
        if (lane == 0) ((float*)&g_sm2[n])[head] = s;
    }
}

// ---------------- rel projection: v_rel = x@M_rel, s_rel ----------------
__global__ void __launch_bounds__(256) k_proj_rel(const float* __restrict__ x,
                           const float* __restrict__ W,
                           const float* __restrict__ b,
                           const float* __restrict__ aedge) {
    __shared__ float sx[32 * DRELN];
    int tid = threadIdx.x, w = tid >> 5, lane = tid & 31;
    int slot = w >> 1, head = w & 1;
    int n0 = blockIdx.x * 32;
    for (int i = tid; i < 32 * DRELN; i += 256) sx[i] = x[n0 * DRELN + i];
    float wreg[DRELN], mreg[DRELN];
#pragma unroll
    for (int k = 0; k < DRELN; k++) {
        wreg[k] = W[k * HD + head * 32 + lane];
        mreg[k] = g_Mrel[k * HD + head * 32 + lane];
    }
    float bb = b[head * 32 + lane];
    float av = aedge[head * 64 + 32 + lane];
    __syncthreads();
    float* vr = (float*)g_vrel4;
    for (int row = slot; row < 32; row += 4) {
        int n = n0 + row;
        float acc = bb, vacc = 0.f;
#pragma unroll
        for (int k = 0; k < DRELN; k++) {
            float xk = sx[row * DRELN + k];
            acc  = fmaf(xk, wreg[k], acc);
            vacc = fmaf(xk, mreg[k], vacc);
        }
        vr[n * HD + head * 32 + lane] = vacc;
        float s = fmaxf(acc, 0.f) * av;
#pragma unroll
        for (int o = 16; o > 0; o >>= 1) s += __shfl_down_sync(0xffffffffu, s, o);
        if (lane == 0) ((float*)&g_sr2[n])[head] = s;
    }
}

// ---------------- edge pass A: logits + segment max ----------------
__global__ void k_edge_logit(const int* __restrict__ src, const int* __restrict__ dst,
                             const int* __restrict__ hn,  const int* __restrict__ he) {
    int e = blockIdx.x * blockDim.x + threadIdx.x;
    if (e >= EE) return;
    int s = src[e], t = dst[e], mn = hn[e], r = he[e];
    float2 es = __ldg(&g_es2[s]);
    float2 ed = __ldg(&g_ed2[t]);
    float2 sm = __ldg(&g_sm2[mn]);
    float2 sr = __ldg(&g_sr2[r]);
    float L0 = es.x + ed.x + sm.x + sr.x;
    float L1 = es.y + ed.y + sm.y + sr.y;
    g_logit2[e] = make_float2(L0, L1);
    atomicMax(&g_m[t * 2 + 0], ford(L0));
    atomicMax(&g_m[t * 2 + 1], ford(L1));
}

// ---------------- edge pass B: exp + denom + unnormalized scatter-sum ----------------
// 16 threads per edge; thread q owns float4 chunk q (cols 4q..4q+3)
__global__ void k_edge_agg(const int* __restrict__ src, const int* __restrict__ dst,
                           const int* __restrict__ hn,  const int* __restrict__ he) {
    long long gtid = (long long)blockIdx.x * blockDim.x + threadIdx.x;
    int e = (int)(gtid >> 4);
    int q = (int)(gtid & 15);
    if (e >= EE) return;
    int s = src[e], t = dst[e], mn = hn[e], r = he[e];
    int h = q >> 3;
    float L  = ((const float*)&g_logit2[e])[h];
    float mx = forddec(g_m[t * 2 + h]);
    float ex = __expf(L - mx);
    if ((q & 7) == 0) atomicAdd(&g_denom[t * 2 + h], ex);
    float4 a = __ldg(&g_hp4[s * 16 + q]);
    float4 bq = __ldg(&g_vmid4[mn * 16 + q]);
    float4 cq = __ldg(&g_vrel4[r * 16 + q]);
    float4 v;
    v.x = ex * (a.x + bq.x + cq.x);
    v.y = ex * (a.y + bq.y + cq.y);
    v.z = ex * (a.z + bq.z + cq.z);
    v.w = ex * (a.w + bq.w + cq.w);
    red_add_v4(((float*)g_rst4) + (size_t)t * HD + q * 4, v);
}

// ---------------- final: /denom, +vb, +b_edge, residual, relu, L2-normalize ----------------
__global__ void k_final(const float* __restrict__ b_edge, float* __restrict__ out) {
    int tid = threadIdx.x;
    int nl  = tid >> 6, c = tid & 63;
    int n   = blockIdx.x * 4 + nl;
    int hd  = c >> 5, d = c & 31;
    float den = g_denom[n * HH + hd];
    float rst = (den > 0.f) ? ((float*)g_rst4)[n * HD + c] / den + g_vb[c] : 0.f;
    float val = fmaxf(rst + b_edge[d] + ((float*)g_hp4)[n * HD + c], 0.f);
    float ss  = val * val;
#pragma unroll
    for (int o = 16; o > 0; o >>= 1) ss += __shfl_down_sync(0xffffffffu, ss, o);
    __shared__ float sp[8];
    if ((tid & 31) == 0) sp[tid >> 5] = ss;
    __syncthreads();
    float tot  = sp[nl * 2] + sp[nl * 2 + 1];
    float norm = fmaxf(sqrtf(tot), 1e-12f);
    out[n * HD + c] = val / norm;
}

extern "C" void kernel_launch(void* const* d_in, const int* in_sizes, int n_in,
                              void* d_out, int out_size) {
    const float* h         = (const float*)d_in[0];
    const float* W_t       = (const float*)d_in[1];
    const float* b_t       = (const float*)d_in[2];
    const float* nfeat_mid = (const float*)d_in[3];
    const float* W_mid     = (const float*)d_in[4];
    const float* b_mid     = (const float*)d_in[5];
    const float* efeat_rel = (const float*)d_in[6];
    const float* W_rel     = (const float*)d_in[7];
    const float* b_rel     = (const float*)d_in[8];
    const float* attn_src  = (const float*)d_in[9];
    const float* attn_dst  = (const float*)d_in[10];
    const float* attn_edge = (const float*)d_in[11];
    const float* W_edge    = (const float*)d_in[12];
    const float* b_edge    = (const float*)d_in[13];
    const int*   src_idx   = (const int*)d_in[14];
    const int*   dst_idx   = (const int*)d_in[15];
    const int*   hn        = (const int*)d_in[16];
    const int*   he        = (const int*)d_in[17];
    float* out = (float*)d_out;

    k_init<<<(NN * 16 + 255) / 256, 256>>>();
    k_prep<<<1, 256>>>(W_mid, W_rel, b_mid, b_rel, W_edge);
    k_proj_target<<<(NN + 31) / 32, 256>>>(h, W_t, b_t, attn_src, attn_dst);
    k_proj_mid<<<NN / 16, 128>>>(nfeat_mid, W_mid, b_mid, attn_edge);
    k_proj_rel<<<ERELN / 32, 256>>>(efeat_rel, W_rel, b_rel, attn_edge);
    k_edge_logit<<<(EE + 255) / 256, 256>>>(src_idx, dst_idx, hn, he);
    k_edge_agg<<<(EE * 16) / 256, 256>>>(src_idx, dst_idx, hn, he);
    k_final<<<NN / 4, 256>>>(b_edge, out);
}

// round 4
// speedup vs baseline: 1.6957x; 1.0061x over previous
#include <cuda_runtime.h>

#define NN     50000
#define EE     800000
#define HH     2
#define DD     32
#define HD     64      // H*D
#define INDIM  64
#define ERELN  200000
#define DRELN  32

// ---------------- scratch (static __device__, no allocation) ----------------
__device__ float4   g_hp4[NN * 16];        // hp, float4-aligned
__device__ float4   g_vmid4[NN * 16];      // x_mid @ M_mid  (bias folded out)
__device__ float4   g_vrel4[ERELN * 16];   // x_rel @ M_rel  (bias folded out)
__device__ float2   g_es2[NN];             // e_src per (n,h)
__device__ float2   g_ed2[NN];             // e_dst
__device__ float2   g_sm2[NN];             // s_mid
__device__ float2   g_sr2[ERELN];          // s_rel
__device__ float2   g_logit2[EE];
__device__ unsigned g_m[NN * HH];
__device__ float    g_denom[NN * HH];
__device__ float4   g_rst4[NN * 16];
__device__ float    g_Mmid[INDIM * HD];    // W_mid @ We[0:32]  per head
__device__ float    g_Mrel[DRELN * HD];    // W_rel @ We[32:64] per head
__device__ float    g_vb[HD];              // (b_mid@We_top + b_rel@We_bot)

__device__ __forceinline__ unsigned ford(float f) {
    unsigned u = __float_as_uint(f);
    return (u >> 31) ? ~u : (u | 0x80000000u);
}
__device__ __forceinline__ float forddec(unsigned u) {
    return __uint_as_float((u >> 31) ? (u & 0x7fffffffu) : ~u);
}
__device__ __forceinline__ void red_add_v4(float* p, float4 v) {
    asm volatile("red.global.add.v4.f32 [%0], {%1,%2,%3,%4};"
                 :: "l"(p), "f"(v.x), "f"(v.y), "f"(v.z), "f"(v.w) : "memory");
}

// ---------------- init ----------------
__global__ void k_init() {
    int i = blockIdx.x * blockDim.x + threadIdx.x;
    if (i < NN * 16) g_rst4[i] = make_float4(0.f, 0.f, 0.f, 0.f);
    if (i < NN * HH) { g_m[i] = 0x007FFFFFu; g_denom[i] = 0.f; }
}

// ---------------- precompute fused weight matrices ----------------
__global__ void k_prep(const float* __restrict__ W_mid, const float* __restrict__ W_rel,
                       const float* __restrict__ b_mid, const float* __restrict__ b_rel,
                       const float* __restrict__ We) {
    __shared__ float sWe[64 * 32];
    int tid = threadIdx.x;
    for (int i = tid; i < 2048; i += 256) sWe[i] = We[i];
    __syncthreads();
    for (int idx = tid; idx < INDIM * HD; idx += 256) {
        int k = idx >> 6, c = idx & 63, h = c >> 5, d = c & 31;
        float acc = 0.f;
        for (int dd = 0; dd < 32; dd++)
            acc = fmaf(W_mid[k * 64 + h * 32 + dd], sWe[dd * 32 + d], acc);
        g_Mmid[idx] = acc;
    }
    for (int idx = tid; idx < DRELN * HD; idx += 256) {
        int k = idx >> 6, c = idx & 63, h = c >> 5, d = c & 31;
        float acc = 0.f;
        for (int dd = 0; dd < 32; dd++)
            acc = fmaf(W_rel[k * 64 + h * 32 + dd], sWe[(32 + dd) * 32 + d], acc);
        g_Mrel[idx] = acc;
    }
    if (tid < HD) {
        int h = tid >> 5, d = tid & 31;
        float acc = 0.f;
        for (int dd = 0; dd < 32; dd++) {
            acc = fmaf(b_mid[h * 32 + dd], sWe[dd * 32 + d], acc);
            acc = fmaf(b_rel[h * 32 + dd], sWe[(32 + dd) * 32 + d], acc);
        }
        g_vb[tid] = acc;
    }
}

// ---------------- target projection: hp, e_src, e_dst ----------------
// 256 thr = 8 warps = 4 row-slots x 2 heads; 32 rows/block; W column in regs
__global__ void __launch_bounds__(256) k_proj_target(const float* __restrict__ x,
                              const float* __restrict__ W,
                              const float* __restrict__ b,
                              const float* __restrict__ asrc,
                              const float* __restrict__ adst) {
    __shared__ float sx[32 * INDIM];
    int tid = threadIdx.x, w = tid >> 5, lane = tid & 31;
    int slot = w >> 1, head = w & 1;
    int n0 = blockIdx.x * 32;
    int nrows = min(32, NN - n0);
    for (int i = tid; i < nrows * INDIM; i += 256) sx[i] = x[n0 * INDIM + i];
    float wreg[INDIM];
#pragma unroll
    for (int k = 0; k < INDIM; k++) wreg[k] = W[k * HD + head * 32 + lane];
    float bb = b[head * 32 + lane];
    float as = asrc[head * 32 + lane], ad = adst[head * 32 + lane];
    __syncthreads();
    float* hp = (float*)g_hp4;
    for (int row = slot; row < nrows; row += 4) {
        int n = n0 + row;
        float acc = bb;
#pragma unroll
        for (int k = 0; k < INDIM; k++) acc = fmaf(sx[row * INDIM + k], wreg[k], acc);
        hp[n * HD + head * 32 + lane] = acc;
        float r = fmaxf(acc, 0.f);
        float vs = r * as, vd = r * ad;
#pragma unroll
        for (int o = 16; o > 0; o >>= 1) {
            vs += __shfl_down_sync(0xffffffffu, vs, o);
            vd += __shfl_down_sync(0xffffffffu, vd, o);
        }
        if (lane == 0) {
            ((float*)&g_es2[n])[head] = vs;
            ((float*)&g_ed2[n])[head] = vd;
        }
    }
}

// ---------------- mid projection: v_mid = x@M_mid, s_mid ----------------
// 128 thr = 4 warps = 2 slots x 2 heads; 16 rows/block
__global__ void __launch_bounds__(128, 3) k_proj_mid(const float* __restrict__ x,
                           const float* __restrict__ W,
                           const float* __restrict__ b,
                           const float* __restrict__ aedge) {
    __shared__ float sx[16 * INDIM];
    int tid = threadIdx.x, w = tid >> 5, lane = tid & 31;
    int slot = w >> 1, head = w & 1;
    int n0 = blockIdx.x * 16;
    for (int i = tid; i < 16 * INDIM; i += 128) sx[i] = x[n0 * INDIM + i];
    float wreg[INDIM], mreg[INDIM];
#pragma unroll
    for (int k = 0; k < INDIM; k++) {
        wreg[k] = W[k * HD + head * 32 + lane];
        mreg[k] = g_Mmid[k * HD + head * 32 + lane];
    }
    float bb = b[head * 32 + lane];
    float av = aedge[head * 64 + lane];
    __syncthreads();
    float* vm = (float*)g_vmid4;
    for (int row = slot; row < 16; row += 2) {
        int n = n0 + row;
        float acc = bb, vacc = 0.f;
#pragma unroll
        for (int k = 0; k < INDIM; k++) {
            float xk = sx[row * INDIM + k];
            acc  = fmaf(xk, wreg[k], acc);
            vacc = fmaf(xk, mreg[k], vacc);
        }
        vm[n * HD + head * 32 + lane] = vacc;
        float s = fmaxf(acc, 0.f) * av;
#pragma unroll
        for (int o = 16; o > 0; o >>= 1) s += __shfl_down_sync(0xffffffffu, s, o);
        if (lane == 0) ((float*)&g_sm2[n])[head] = s;
    }
}

// ---------------- rel projection: v_rel = x@M_rel, s_rel ----------------
__global__ void __launch_bounds__(256) k_proj_rel(const float* __restrict__ x,
                           const float* __restrict__ W,
                           const float* __restrict__ b,
                           const float* __restrict__ aedge) {
    __shared__ float sx[32 * DRELN];
    int tid = threadIdx.x, w = tid >> 5, lane = tid & 31;
    int slot = w >> 1, head = w & 1;
    int n0 = blockIdx.x * 32;
    for (int i = tid; i < 32 * DRELN; i += 256) sx[i] = x[n0 * DRELN + i];
    float wreg[DRELN], mreg[DRELN];
#pragma unroll
    for (int k = 0; k < DRELN; k++) {
        wreg[k] = W[k * HD + head * 32 + lane];
        mreg[k] = g_Mrel[k * HD + head * 32 + lane];
    }
    float bb = b[head * 32 + lane];
    float av = aedge[head * 64 + 32 + lane];
    __syncthreads();
    float* vr = (float*)g_vrel4;
    for (int row = slot; row < 32; row += 4) {
        int n = n0 + row;
        float acc = bb, vacc = 0.f;
#pragma unroll
        for (int k = 0; k < DRELN; k++) {
            float xk = sx[row * DRELN + k];
            acc  = fmaf(xk, wreg[k], acc);
            vacc = fmaf(xk, mreg[k], vacc);
        }
        vr[n * HD + head * 32 + lane] = vacc;
        float s = fmaxf(acc, 0.f) * av;
#pragma unroll
        for (int o = 16; o > 0; o >>= 1) s += __shfl_down_sync(0xffffffffu, s, o);
        if (lane == 0) ((float*)&g_sr2[n])[head] = s;
    }
}

// ---------------- edge pass A: logits + segment max ----------------
__global__ void k_edge_logit(const int* __restrict__ src, const int* __restrict__ dst,
                             const int* __restrict__ hn,  const int* __restrict__ he) {
    int e = blockIdx.x * blockDim.x + threadIdx.x;
    if (e >= EE) return;
    int s = src[e], t = dst[e], mn = hn[e], r = he[e];
    float2 es = __ldg(&g_es2[s]);
    float2 ed = __ldg(&g_ed2[t]);
    float2 sm = __ldg(&g_sm2[mn]);
    float2 sr = __ldg(&g_sr2[r]);
    float L0 = es.x + ed.x + sm.x + sr.x;
    float L1 = es.y + ed.y + sm.y + sr.y;
    g_logit2[e] = make_float2(L0, L1);
    atomicMax(&g_m[t * 2 + 0], ford(L0));
    atomicMax(&g_m[t * 2 + 1], ford(L1));
}

// ---------------- edge pass B: exp + denom + unnormalized scatter-sum ----------------
// 16 threads per edge; thread q owns float4 chunk q (cols 4q..4q+3)
__global__ void k_edge_agg(const int* __restrict__ src, const int* __restrict__ dst,
                           const int* __restrict__ hn,  const int* __restrict__ he) {
    long long gtid = (long long)blockIdx.x * blockDim.x + threadIdx.x;
    int e = (int)(gtid >> 4);
    int q = (int)(gtid & 15);
    if (e >= EE) return;
    int s = src[e], t = dst[e], mn = hn[e], r = he[e];
    int h = q >> 3;
    float L  = ((const float*)&g_logit2[e])[h];
    float mx = forddec(g_m[t * 2 + h]);
    float ex = __expf(L - mx);
    if ((q & 7) == 0) atomicAdd(&g_denom[t * 2 + h], ex);
    float4 a = __ldg(&g_hp4[s * 16 + q]);
    float4 bq = __ldg(&g_vmid4[mn * 16 + q]);
    float4 cq = __ldg(&g_vrel4[r * 16 + q]);
    float4 v;
    v.x = ex * (a.x + bq.x + cq.x);
    v.y = ex * (a.y + bq.y + cq.y);
    v.z = ex * (a.z + bq.z + cq.z);
    v.w = ex * (a.w + bq.w + cq.w);
    red_add_v4(((float*)g_rst4) + (size_t)t * HD + q * 4, v);
}

// ---------------- final: /denom, +vb, +b_edge, residual, relu, L2-normalize ----------------
__global__ void k_final(const float* __restrict__ b_edge, float* __restrict__ out) {
    int tid = threadIdx.x;
    int nl  = tid >> 6, c = tid & 63;
    int n   = blockIdx.x * 4 + nl;
    int hd  = c >> 5, d = c & 31;
    float den = g_denom[n * HH + hd];
    float rst = (den > 0.f) ? ((float*)g_rst4)[n * HD + c] / den + g_vb[c] : 0.f;
    float val = fmaxf(rst + b_edge[d] + ((float*)g_hp4)[n * HD + c], 0.f);
    float ss  = val * val;
#pragma unroll
    for (int o = 16; o > 0; o >>= 1) ss += __shfl_down_sync(0xffffffffu, ss, o);
    __shared__ float sp[8];
    if ((tid & 31) == 0) sp[tid >> 5] = ss;
    __syncthreads();
    float tot  = sp[nl * 2] + sp[nl * 2 + 1];
    float norm = fmaxf(sqrtf(tot), 1e-12f);
    out[n * HD + c] = val / norm;
}

extern "C" void kernel_launch(void* const* d_in, const int* in_sizes, int n_in,
                              void* d_out, int out_size) {
    const float* h         = (const float*)d_in[0];
    const float* W_t       = (const float*)d_in[1];
    const float* b_t       = (const float*)d_in[2];
    const float* nfeat_mid = (const float*)d_in[3];
    const float* W_mid     = (const float*)d_in[4];
    const float* b_mid     = (const float*)d_in[5];
    const float* efeat_rel = (const float*)d_in[6];
    const float* W_rel     = (const float*)d_in[7];
    const float* b_rel     = (const float*)d_in[8];
    const float* attn_src  = (const float*)d_in[9];
    const float* attn_dst  = (const float*)d_in[10];
    const float* attn_edge = (const float*)d_in[11];
    const float* W_edge    = (const float*)d_in[12];
    const float* b_edge    = (const float*)d_in[13];
    const int*   src_idx   = (const int*)d_in[14];
    const int*   dst_idx   = (const int*)d_in[15];
    const int*   hn        = (const int*)d_in[16];
    const int*   he        = (const int*)d_in[17];
    float* out = (float*)d_out;

    k_init<<<(NN * 16 + 255) / 256, 256>>>();
    k_prep<<<1, 256>>>(W_mid, W_rel, b_mid, b_rel, W_edge);
    k_proj_target<<<(NN + 31) / 32, 256>>>(h, W_t, b_t, attn_src, attn_dst);
    k_proj_mid<<<NN / 16, 128>>>(nfeat_mid, W_mid, b_mid, attn_edge);
    k_proj_rel<<<ERELN / 32, 256>>>(efeat_rel, W_rel, b_rel, attn_edge);
    k_edge_logit<<<(EE + 255) / 256, 256>>>(src_idx, dst_idx, hn, he);
    k_edge_agg<<<(EE * 16) / 256, 256>>>(src_idx, dst_idx, hn, he);
    k_final<<<NN / 4, 256>>>(b_edge, out);
}

// round 5
// speedup vs baseline: 2.3210x; 1.3687x over previous
#include <cuda_runtime.h>

typedef unsigned long long u64;

#define NN     50000
#define EE     800000
#define HH     2
#define DD     32
#define HD     64      // H*D
#define INDIM  64
#define ERELN  200000
#define DRELN  32

// ---------------- scratch (static __device__, no allocation) ----------------
__device__ float4   g_hp4[NN * 16];
__device__ float4   g_vmid4[NN * 16];
__device__ float4   g_vrel4[ERELN * 16];
__device__ float2   g_es2[NN];
__device__ float2   g_ed2[NN];
__device__ float2   g_sm2[NN];
__device__ float2   g_sr2[ERELN];
__device__ float2   g_denom2[NN];
__device__ float4   g_rst4[NN * 16];
__device__ float    g_Mmid[INDIM * HD];
__device__ float    g_Mrel[DRELN * HD];
__device__ float    g_vb[HD];

// ---------------- f32x2 helpers ----------------
__device__ __forceinline__ u64 pack2(float lo, float hi) {
    u64 r; asm("mov.b64 %0, {%1,%2};" : "=l"(r) : "f"(lo), "f"(hi)); return r;
}
__device__ __forceinline__ void unpack2(u64 v, float& lo, float& hi) {
    asm("mov.b64 {%0,%1}, %2;" : "=f"(lo), "=f"(hi) : "l"(v));
}
__device__ __forceinline__ void ffma2(u64& d, u64 a, u64 b) {
    asm("fma.rn.f32x2 %0, %1, %2, %0;" : "+l"(d) : "l"(a), "l"(b));
}
__device__ __forceinline__ u64 addf32x2(u64 a, u64 b) {
    u64 r; asm("add.rn.f32x2 %0, %1, %2;" : "=l"(r) : "l"(a), "l"(b)); return r;
}
__device__ __forceinline__ void red_add_v4(float* p, float4 v) {
    asm volatile("red.global.add.v4.f32 [%0], {%1,%2,%3,%4};"
                 :: "l"(p), "f"(v.x), "f"(v.y), "f"(v.z), "f"(v.w) : "memory");
}
__device__ __forceinline__ void red_add_v2(float2* p, float a, float b) {
    asm volatile("red.global.add.v2.f32 [%0], {%1,%2};"
                 :: "l"(p), "f"(a), "f"(b) : "memory");
}

// ---------------- init + prep (block 0 = prep, rest = init) ----------------
__global__ void k_init_prep(const float* __restrict__ W_mid, const float* __restrict__ W_rel,
                            const float* __restrict__ b_mid, const float* __restrict__ b_rel,
                            const float* __restrict__ We) {
    int tid = threadIdx.x;
    if (blockIdx.x == 0) {
        __shared__ float sWe[64 * 32];
        for (int i = tid; i < 2048; i += 256) sWe[i] = We[i];
        __syncthreads();
        for (int idx = tid; idx < INDIM * HD; idx += 256) {
            int k = idx >> 6, c = idx & 63, h = c >> 5, d = c & 31;
            float acc = 0.f;
            for (int dd = 0; dd < 32; dd++)
                acc = fmaf(W_mid[k * 64 + h * 32 + dd], sWe[dd * 32 + d], acc);
            g_Mmid[idx] = acc;
        }
        for (int idx = tid; idx < DRELN * HD; idx += 256) {
            int k = idx >> 6, c = idx & 63, h = c >> 5, d = c & 31;
            float acc = 0.f;
            for (int dd = 0; dd < 32; dd++)
                acc = fmaf(W_rel[k * 64 + h * 32 + dd], sWe[(32 + dd) * 32 + d], acc);
            g_Mrel[idx] = acc;
        }
        if (tid < HD) {
            int h = tid >> 5, d = tid & 31;
            float acc = 0.f;
            for (int dd = 0; dd < 32; dd++) {
                acc = fmaf(b_mid[h * 32 + dd], sWe[dd * 32 + d], acc);
                acc = fmaf(b_rel[h * 32 + dd], sWe[(32 + dd) * 32 + d], acc);
            }
            g_vb[tid] = acc;
        }
    } else {
        int i = (blockIdx.x - 1) * 256 + tid;
        if (i < NN * 16) g_rst4[i] = make_float4(0.f, 0.f, 0.f, 0.f);
        if (i < NN)      g_denom2[i] = make_float2(0.f, 0.f);
    }
}

// ---------------- target projection: hp, e_src, e_dst ----------------
__global__ void __launch_bounds__(256) k_proj_target(const float* __restrict__ x,
                              const float* __restrict__ W,
                              const float* __restrict__ b,
                              const float* __restrict__ asrc,
                              const float* __restrict__ adst) {
    __shared__ float sx[32 * INDIM];
    int tid = threadIdx.x, w = tid >> 5, lane = tid & 31;
    int slot = w >> 1, head = w & 1;
    int n0 = blockIdx.x * 32;
    int nrows = min(32, NN - n0);
    for (int i = tid; i < nrows * INDIM; i += 256) sx[i] = x[n0 * INDIM + i];
    int col = head * 32 + lane;
    float wreg[INDIM];
#pragma unroll
    for (int k = 0; k < INDIM; k++) wreg[k] = W[k * HD + col];
    float bb = b[col];
    float as = asrc[col], ad = adst[col];
    __syncthreads();
    float* hp = (float*)g_hp4;
    for (int row = slot; row < nrows; row += 4) {
        int n = n0 + row;
        float a0 = bb, a1 = 0.f;
        const float4* xr = (const float4*)(sx + row * INDIM);
#pragma unroll
        for (int k4 = 0; k4 < 16; k4++) {
            float4 xv = xr[k4];
            a0 = fmaf(xv.x, wreg[4 * k4 + 0], a0);
            a1 = fmaf(xv.y, wreg[4 * k4 + 1], a1);
            a0 = fmaf(xv.z, wreg[4 * k4 + 2], a0);
            a1 = fmaf(xv.w, wreg[4 * k4 + 3], a1);
        }
        float acc = a0 + a1;
        hp[n * HD + col] = acc;
        float r = fmaxf(acc, 0.f);
        float vs = r * as, vd = r * ad;
#pragma unroll
        for (int o = 16; o > 0; o >>= 1) {
            vs += __shfl_down_sync(0xffffffffu, vs, o);
            vd += __shfl_down_sync(0xffffffffu, vd, o);
        }
        if (lane == 0) {
            ((float*)&g_es2[n])[head] = vs;
            ((float*)&g_ed2[n])[head] = vd;
        }
    }
}

// ---------------- mid projection: (acc, vacc) via FFMA2, K split across 2 warps ----------------
// 128 thr = 4 warps: head = w&1, kh = w>>1; 16 rows/block
__global__ void __launch_bounds__(128) k_proj_mid(const float* __restrict__ x,
                           const float* __restrict__ W,
                           const float* __restrict__ b,
                           const float* __restrict__ aedge) {
    __shared__ float sx[16 * INDIM];
    __shared__ u64 sp[2][16][64];
    int tid = threadIdx.x, w = tid >> 5, lane = tid & 31;
    int head = w & 1, kh = w >> 1;
    int n0 = blockIdx.x * 16;
    {   // 1024 floats = 256 float4, 2 per thread
        const float4* xs = (const float4*)(x + (size_t)n0 * INDIM);
        float4* sx4 = (float4*)sx;
        sx4[tid] = xs[tid];
        sx4[tid + 128] = xs[tid + 128];
    }
    int col = head * 32 + lane;
    u64 wm[32];
#pragma unroll
    for (int kk = 0; kk < 32; kk++) {
        int k = kh * 32 + kk;
        wm[kk] = pack2(W[k * HD + col], g_Mmid[k * HD + col]);
    }
    __syncthreads();
    for (int row = 0; row < 16; row++) {
        u64 d0 = 0, d1 = 0;
        const float4* xr = (const float4*)(sx + row * INDIM + kh * 32);
#pragma unroll
        for (int k4 = 0; k4 < 8; k4++) {
            float4 xv = xr[k4];
            ffma2(d0, pack2(xv.x, xv.x), wm[4 * k4 + 0]);
            ffma2(d1, pack2(xv.y, xv.y), wm[4 * k4 + 1]);
            ffma2(d0, pack2(xv.z, xv.z), wm[4 * k4 + 2]);
            ffma2(d1, pack2(xv.w, xv.w), wm[4 * k4 + 3]);
        }
        sp[kh][row][col] = addf32x2(d0, d1);
    }
    __syncthreads();
    if (kh == 0) {
        float bb = b[col];
        float av = aedge[head * 64 + lane];
        float* vm = (float*)g_vmid4;
        for (int row = 0; row < 16; row++) {
            u64 p = addf32x2(sp[0][row][col], sp[1][row][col]);
            float acc, vacc; unpack2(p, acc, vacc);
            acc += bb;
            int n = n0 + row;
            vm[n * HD + col] = vacc;
            float s = fmaxf(acc, 0.f) * av;
#pragma unroll
            for (int o = 16; o > 0; o >>= 1) s += __shfl_down_sync(0xffffffffu, s, o);
            if (lane == 0) ((float*)&g_sm2[n])[head] = s;
        }
    }
}

// ---------------- rel projection: FFMA2, K=32 in regs ----------------
// 128 thr = 4 warps: 2 slots x 2 heads; 32 rows/block
__global__ void __launch_bounds__(128) k_proj_rel(const float* __restrict__ x,
                           const float* __restrict__ W,
                           const float* __restrict__ b,
                           const float* __restrict__ aedge) {
    __shared__ float sx[32 * DRELN];
    int tid = threadIdx.x, w = tid >> 5, lane = tid & 31;
    int slot = w >> 1, head = w & 1;
    int n0 = blockIdx.x * 32;
    {   // 1024 floats = 256 float4
        const float4* xs = (const float4*)(x + (size_t)n0 * DRELN);
        float4* sx4 = (float4*)sx;
        sx4[tid] = xs[tid];
        sx4[tid + 128] = xs[tid + 128];
    }
    int col = head * 32 + lane;
    u64 wm[32];
#pragma unroll
    for (int k = 0; k < DRELN; k++)
        wm[k] = pack2(W[k * HD + col], g_Mrel[k * HD + col]);
    float bb = b[col];
    float av = aedge[head * 64 + 32 + lane];
    __syncthreads();
    float* vr = (float*)g_vrel4;
    for (int row = slot; row < 32; row += 2) {
        int n = n0 + row;
        u64 d0 = 0, d1 = 0;
        const float4* xr = (const float4*)(sx + row * DRELN);
#pragma unroll
        for (int k4 = 0; k4 < 8; k4++) {
            float4 xv = xr[k4];
            ffma2(d0, pack2(xv.x, xv.x), wm[4 * k4 + 0]);
            ffma2(d1, pack2(xv.y, xv.y), wm[4 * k4 + 1]);
            ffma2(d0, pack2(xv.z, xv.z), wm[4 * k4 + 2]);
            ffma2(d1, pack2(xv.w, xv.w), wm[4 * k4 + 3]);
        }
        float acc, vacc; unpack2(addf32x2(d0, d1), acc, vacc);
        acc += bb;
        vr[n * HD + col] = vacc;
        float s = fmaxf(acc, 0.f) * av;
#pragma unroll
        for (int o = 16; o > 0; o >>= 1) s += __shfl_down_sync(0xffffffffu, s, o);
        if (lane == 0) ((float*)&g_sr2[n])[head] = s;
    }
}

// ---------------- fused edge pass: logits + exp (no max) + denom + weighted scatter ----------------
// 16 threads per edge; lane group [0..15]/[16..31]; q==0 computes ex0/ex1, shfl broadcast
__global__ void k_edge_agg(const int* __restrict__ src, const int* __restrict__ dst,
                           const int* __restrict__ hn,  const int* __restrict__ he) {
    int gt = blockIdx.x * 256 + threadIdx.x;
    int e = gt >> 4;
    int q = gt & 15;
    int lane = threadIdx.x & 31;
    int s = src[e], t = dst[e], mn = hn[e], r = he[e];
    float ex0 = 0.f, ex1 = 0.f;
    if (q == 0) {
        float2 es = __ldg(&g_es2[s]);
        float2 ed = __ldg(&g_ed2[t]);
        float2 sm = __ldg(&g_sm2[mn]);
        float2 sr = __ldg(&g_sr2[r]);
        ex0 = __expf(es.x + ed.x + sm.x + sr.x);
        ex1 = __expf(es.y + ed.y + sm.y + sr.y);
        red_add_v2(&g_denom2[t], ex0, ex1);
    }
    int base = lane & ~15;
    ex0 = __shfl_sync(0xffffffffu, ex0, base);
    ex1 = __shfl_sync(0xffffffffu, ex1, base);
    float ex = (q & 8) ? ex1 : ex0;
    float4 a  = __ldg(&g_hp4[s * 16 + q]);
    float4 bq = __ldg(&g_vmid4[mn * 16 + q]);
    float4 cq = __ldg(&g_vrel4[r * 16 + q]);
    float4 v;
    v.x = ex * (a.x + bq.x + cq.x);
    v.y = ex * (a.y + bq.y + cq.y);
    v.z = ex * (a.z + bq.z + cq.z);
    v.w = ex * (a.w + bq.w + cq.w);
    red_add_v4(((float*)g_rst4) + (size_t)t * HD + q * 4, v);
}

// ---------------- final: /denom, +vb, +b_edge, residual, relu, L2-normalize ----------------
__global__ void k_final(const float* __restrict__ b_edge, float* __restrict__ out) {
    int tid = threadIdx.x;
    int nl  = tid >> 6, c = tid & 63;
    int n   = blockIdx.x * 4 + nl;
    int hd  = c >> 5, d = c & 31;
    float den = ((const float*)&g_denom2[n])[hd];
    float rst = (den > 0.f) ? ((float*)g_rst4)[n * HD + c] / den + g_vb[c] : 0.f;
    float val = fmaxf(rst + b_edge[d] + ((float*)g_hp4)[n * HD + c], 0.f);
    float ss  = val * val;
#pragma unroll
    for (int o = 16; o > 0; o >>= 1) ss += __shfl_down_sync(0xffffffffu, ss, o);
    __shared__ float sp[8];
    if ((tid & 31) == 0) sp[tid >> 5] = ss;
    __syncthreads();
    float tot  = sp[nl * 2] + sp[nl * 2 + 1];
    float norm = fmaxf(sqrtf(tot), 1e-12f);
    out[n * HD + c] = val / norm;
}

extern "C" void kernel_launch(void* const* d_in, const int* in_sizes, int n_in,
                              void* d_out, int out_size) {
    const float* h         = (const float*)d_in[0];
    const float* W_t       = (const float*)d_in[1];
    const float* b_t       = (const float*)d_in[2];
    const float* nfeat_mid = (const float*)d_in[3];
    const float* W_mid     = (const float*)d_in[4];
    const float* b_mid     = (const float*)d_in[5];
    const float* efeat_rel = (const float*)d_in[6];
    const float* W_rel     = (const float*)d_in[7];
    const float* b_rel     = (const float*)d_in[8];
    const float* attn_src  = (const float*)d_in[9];
    const float* attn_dst  = (const float*)d_in[10];
    const float* attn_edge = (const float*)d_in[11];
    const float* W_edge    = (const float*)d_in[12];
    const float* b_edge    = (const float*)d_in[13];
    const int*   src_idx   = (const int*)d_in[14];
    const int*   dst_idx   = (const int*)d_in[15];
    const int*   hn        = (const int*)d_in[16];
    const int*   he        = (const int*)d_in[17];
    float* out = (float*)d_out;

    k_init_prep<<<3126, 256>>>(W_mid, W_rel, b_mid, b_rel, W_edge);
    k_proj_target<<<(NN + 31) / 32, 256>>>(h, W_t, b_t, attn_src, attn_dst);
    k_proj_mid<<<NN / 16, 128>>>(nfeat_mid, W_mid, b_mid, attn_edge);
    k_proj_rel<<<ERELN / 32, 128>>>(efeat_rel, W_rel, b_rel, attn_edge);
    k_edge_agg<<<(EE * 16) / 256, 256>>>(src_idx, dst_idx, hn, he);
    k_final<<<NN / 4, 256>>>(b_edge, out);
}